// round 16
// baseline (speedup 1.0000x reference)
#include <cuda_runtime.h>
#include <cuda_fp16.h>
#include <math.h>
#include <stdint.h>

#define N_NODES  50000
#define N_EDGES  600000
#define NF       128
#define N_GRAPHS 256
#define DIM      95
#define N_OUT    12
#define N_ITERS  10
#define BN_EPS   1e-5f
#define SCAN_NBLK 196
#define NTILES   391             // ceil(50000/128)
#define CNT_BLK  512             // edge-count blocks
#define CVT_BLK  64              // x->fp16 conversion blocks (concurrent)

// ---------------- scratch (zero-initialized at load; self-cleaning) --------
__device__ unsigned g_x16[N_NODES * 64];   // x as fp16x2 (2 uints = 4 feats)
__device__ unsigned g_a16[N_NODES * 64];   // fp16x2 packed: (x+agg)
__device__ int   g_counts[N_NODES];        // zeroed by scanAB after use
__device__ int   g_offsets[N_NODES + 1];   // block-local prefixes
__device__ int   g_cursor[N_NODES];
__device__ int   g_srcidx[N_EDGES];
__device__ int   g_bsums[SCAN_NBLK];
__device__ int   g_bpre[SCAN_NBLK];
__device__ float g_stats[2 * NF];          // zeroed by recur last block
__device__ float g_gsum[N_GRAPHS * NF];    // zeroed by its recur block
__device__ int   g_tickA;                  // self-resetting tickets
__device__ int   g_tickR;

// ---------------- helpers ----------------
__device__ __forceinline__ uint32_t smem_u32(const void* p) {
    uint32_t a;
    asm("{ .reg .u64 t; cvta.to.shared.u64 t, %1; cvt.u32.u64 %0, t; }" : "=r"(a) : "l"(p));
    return a;
}
__device__ __forceinline__ void ldsm_x4(uint32_t* r, uint32_t addr) {
    asm volatile("ldmatrix.sync.aligned.m8n8.x4.shared.b16 {%0,%1,%2,%3}, [%4];"
        : "=r"(r[0]), "=r"(r[1]), "=r"(r[2]), "=r"(r[3]) : "r"(addr));
}
__device__ __forceinline__ void ldsm_x4_t(uint32_t* r, uint32_t addr) {
    asm volatile("ldmatrix.sync.aligned.m8n8.x4.trans.shared.b16 {%0,%1,%2,%3}, [%4];"
        : "=r"(r[0]), "=r"(r[1]), "=r"(r[2]), "=r"(r[3]) : "r"(addr));
}
__device__ __forceinline__ void mma_f16(float* c, const uint32_t* a,
                                        uint32_t b0, uint32_t b1) {
    asm volatile("mma.sync.aligned.m16n8k16.row.col.f32.f16.f16.f32 "
        "{%0,%1,%2,%3}, {%4,%5,%6,%7}, {%8,%9}, {%0,%1,%2,%3};"
        : "+f"(c[0]), "+f"(c[1]), "+f"(c[2]), "+f"(c[3])
        : "r"(a[0]), "r"(a[1]), "r"(a[2]), "r"(a[3]), "r"(b0), "r"(b1));
}
__device__ __forceinline__ void cp_async16(uint32_t dst, const void* src, int srcsz) {
    asm volatile("cp.async.cg.shared.global [%0], [%1], 16, %2;"
        :: "r"(dst), "l"(src), "r"(srcsz) : "memory");
}
#define CP_COMMIT() asm volatile("cp.async.commit_group;" ::: "memory")
#define CP_WAIT0()  asm volatile("cp.async.wait_group 0;" ::: "memory")
__device__ __forceinline__ int load_index(const void* p, long long i, int is64) {
    if (is64) return (int)((const long long*)p)[i];
    return ((const int*)p)[i];
}
__device__ __forceinline__ int probe_is64(const void* p) {
    const int* w32 = (const int*)p;
    int bad = 0;
    for (int j = threadIdx.x; j < 1024; j += blockDim.x)
        if (w32[2 * j + 1] != 0) bad = 1;
    return !__syncthreads_or(bad);
}
__device__ __forceinline__ unsigned long long pack_f32x2(float lo, float hi) {
    unsigned long long u;
    asm("mov.b64 %0, {%1, %2};" : "=l"(u) : "f"(lo), "f"(hi));
    return u;
}
__device__ __forceinline__ void unpack_f32x2(unsigned long long u, float& lo, float& hi) {
    asm("mov.b64 {%0, %1}, %2;" : "=f"(lo), "=f"(hi) : "l"(u));
}
__device__ __forceinline__ unsigned pack_h2(float a, float b) {
    __half ha = __float2half_rn(a), hb = __float2half_rn(b);
    return (unsigned)__half_as_ushort(ha) | ((unsigned)__half_as_ushort(hb) << 16);
}

// ---------------- count (blocks 0..511) + x->fp16 convert (blocks 512+) ----
// The two groups do disjoint work concurrently: edge-count is atomic-latency
// bound (~1% BW), conversion is a pure 38MB stream -> they overlap cleanly.
__global__ void count_kernel(const void* ei, const float4* __restrict__ x4) {
    int is64 = probe_is64(ei);
    if (blockIdx.x < CNT_BLK) {
        for (int e = blockIdx.x * blockDim.x + threadIdx.x; e < N_EDGES;
             e += CNT_BLK * blockDim.x) {
            int d = load_index(ei, (long long)N_EDGES + e, is64);
            atomicAdd(&g_counts[d], 1);
        }
    } else {
        uint2* xv = (uint2*)g_x16;
        int cb = blockIdx.x - CNT_BLK;
        for (int i = cb * blockDim.x + threadIdx.x; i < N_NODES * 32;
             i += CVT_BLK * blockDim.x) {
            float4 v = x4[i];
            xv[i] = make_uint2(pack_h2(v.x, v.y), pack_h2(v.z, v.w));
        }
    }
}

// ---------------- fused scan ----------------
__global__ void scanAB_kernel() {
    __shared__ int ws[8];
    __shared__ int amLast;
    int t = threadIdx.x, lane = t & 31, w = t >> 5;
    int i = blockIdx.x * 256 + t;
    int v = (i < N_NODES) ? g_counts[i] : 0;
    if (i < N_NODES) g_counts[i] = 0;
    int x = v;
#pragma unroll
    for (int o = 1; o < 32; o <<= 1) {
        int y = __shfl_up_sync(0xffffffffu, x, o);
        if (lane >= o) x += y;
    }
    if (lane == 31) ws[w] = x;
    __syncthreads();
    if (w == 0) {
        int y = (lane < 8) ? ws[lane] : 0;
#pragma unroll
        for (int o = 1; o < 32; o <<= 1) {
            int z = __shfl_up_sync(0xffffffffu, y, o);
            if (lane >= o) y += z;
        }
        if (lane < 8) ws[lane] = y;
    }
    __syncthreads();
    int pre = ((w > 0) ? ws[w - 1] : 0) + x - v;
    if (i <= N_NODES) g_offsets[i] = pre;
    if (i < N_NODES) g_cursor[i] = pre;
    if (t == 255) g_bsums[blockIdx.x] = ws[7];

    if (t == 0) {
        __threadfence();
        int k = atomicAdd(&g_tickA, 1);
        amLast = (k == SCAN_NBLK - 1);
        if (amLast) __threadfence();
    }
    __syncthreads();
    if (amLast) {
        int v2 = (t < SCAN_NBLK) ? g_bsums[t] : 0;
        int x2 = v2;
#pragma unroll
        for (int o = 1; o < 32; o <<= 1) {
            int y = __shfl_up_sync(0xffffffffu, x2, o);
            if (lane >= o) x2 += y;
        }
        __syncthreads();
        if (lane == 31) ws[w] = x2;
        __syncthreads();
        if (w == 0) {
            int y = (lane < 8) ? ws[lane] : 0;
#pragma unroll
            for (int o = 1; o < 32; o <<= 1) {
                int z = __shfl_up_sync(0xffffffffu, y, o);
                if (lane >= o) y += z;
            }
            if (lane < 8) ws[lane] = y;
        }
        __syncthreads();
        if (t < SCAN_NBLK) g_bpre[t] = ((w > 0) ? ws[w - 1] : 0) + x2 - v2;
        if (t == 0) g_tickA = 0;
    }
}

// ---------------- CSR: scatter ----------------
__global__ void scatter_kernel(const void* ei) {
    int is64 = probe_is64(ei);
    for (int e = blockIdx.x * blockDim.x + threadIdx.x; e < N_EDGES;
         e += gridDim.x * blockDim.x) {
        int s = load_index(ei, e, is64);
        int d = load_index(ei, (long long)N_EDGES + e, is64);
        int pos = g_bpre[d >> 8] + atomicAdd(&g_cursor[d], 1);
        g_srcidx[pos] = s;
    }
}

// ---------------- GIN aggregation: fp16 gather + fp16 self -> fp16 ---------
__global__ void agg_kernel() {
    int node = blockIdx.x * 8 + (threadIdx.x >> 5);
    int lane = threadIdx.x & 31;
    if (node >= N_NODES) return;
    const uint2* xv = (const uint2*)g_x16;
    uint2 su = xv[node * 32 + lane];
    float2 sa = __half22float2(*(__half2*)&su.x);
    float2 sb = __half22float2(*(__half2*)&su.y);
    float acc0 = sa.x, acc1 = sa.y, acc2 = sb.x, acc3 = sb.y;
    int e0 = g_offsets[node] + g_bpre[node >> 8];
    int e1 = g_offsets[node + 1] + g_bpre[(node + 1) >> 8];
    int e = e0;
    int n4 = e0 + ((e1 - e0) & ~3);
    for (; e < n4; e += 4) {
        int s0 = g_srcidx[e], s1 = g_srcidx[e + 1];
        int s2 = g_srcidx[e + 2], s3 = g_srcidx[e + 3];
        uint2 u0 = xv[s0 * 32 + lane];
        uint2 u1 = xv[s1 * 32 + lane];
        uint2 u2 = xv[s2 * 32 + lane];
        uint2 u3 = xv[s3 * 32 + lane];
        float2 f0a = __half22float2(*(__half2*)&u0.x);
        float2 f0b = __half22float2(*(__half2*)&u0.y);
        float2 f1a = __half22float2(*(__half2*)&u1.x);
        float2 f1b = __half22float2(*(__half2*)&u1.y);
        float2 f2a = __half22float2(*(__half2*)&u2.x);
        float2 f2b = __half22float2(*(__half2*)&u2.y);
        float2 f3a = __half22float2(*(__half2*)&u3.x);
        float2 f3b = __half22float2(*(__half2*)&u3.y);
        acc0 += (f0a.x + f1a.x) + (f2a.x + f3a.x);
        acc1 += (f0a.y + f1a.y) + (f2a.y + f3a.y);
        acc2 += (f0b.x + f1b.x) + (f2b.x + f3b.x);
        acc3 += (f0b.y + f1b.y) + (f2b.y + f3b.y);
    }
    for (; e < e1; e++) {
        int s = g_srcidx[e];
        uint2 u = xv[s * 32 + lane];
        float2 fa = __half22float2(*(__half2*)&u.x);
        float2 fb = __half22float2(*(__half2*)&u.y);
        acc0 += fa.x; acc1 += fa.y; acc2 += fb.x; acc3 += fb.y;
    }
    uint2 pv = make_uint2(pack_h2(acc0, acc1), pack_h2(acc2, acc3));
    ((uint2*)g_a16)[node * 32 + lane] = pv;
}

// ---------------- fused dual GEMM (nn1 both layers), single fp16 -----------
#define SA      0                 /* A/t1/x1 tile: 128 x 272B = 34816 */
#define SWA     34816
#define SWB     69632
#define SBIAS1  104448
#define SBIAS2  104960
#define SBATCH  105472
#define GEMM_SMEM 105984

__device__ __forceinline__ void mainloop_f16(uint32_t sbase, uint32_t wBase,
                                             uint32_t lOff, int m0, int n0,
                                             float c[2][8][4]) {
#pragma unroll
    for (int mh = 0; mh < 2; mh++)
#pragma unroll
        for (int j = 0; j < 8; j++)
#pragma unroll
            for (int q = 0; q < 4; q++) c[mh][j][q] = 0.f;

#pragma unroll
    for (int ks = 0; ks < 8; ks++) {
        uint32_t a[2][4];
#pragma unroll
        for (int mh = 0; mh < 2; mh++)
            ldsm_x4(a[mh], sbase + SA + (uint32_t)(m0 + mh * 16) * 272 +
                           (uint32_t)ks * 32 + lOff);
#pragma unroll
        for (int nj = 0; nj < 4; nj++) {
            uint32_t b[4];
            ldsm_x4_t(b, sbase + wBase + (uint32_t)ks * 16 * 272 +
                         (uint32_t)(n0 + nj * 16) * 2 + lOff);
#pragma unroll
            for (int mh = 0; mh < 2; mh++) {
                mma_f16(c[mh][2 * nj],     a[mh], b[0], b[1]);
                mma_f16(c[mh][2 * nj + 1], a[mh], b[2], b[3]);
            }
        }
    }
}

__global__ __launch_bounds__(256, 2) void gemm_fused_kernel(
        const unsigned* __restrict__ A16,
        const float* __restrict__ W1a, const float* __restrict__ b1a,
        const float* __restrict__ W1b, const float* __restrict__ b1b,
        const void* __restrict__ batch, int M) {
    extern __shared__ char smem[];
    uint32_t sbase = smem_u32(smem);
    float* sBias1 = (float*)(smem + SBIAS1);
    float* sBias2 = (float*)(smem + SBIAS2);
    int* sB = (int*)(smem + SBATCH);
    int t = threadIdx.x;
    int lane = t & 31;
    int w = t >> 5;
    int wr = w >> 1, wc = w & 1;
    int m0 = wr * 32, n0 = wc * 64;
    int is64 = probe_is64(batch);

    {
        int tile0 = blockIdx.x;
        if (tile0 < NTILES) {
            int row0 = tile0 << 7;
            for (int idx = t; idx < 2048; idx += 256) {
                int r = idx >> 4, c4 = idx & 15;
                int gr = row0 + r;
                int ok = (gr < M) ? 16 : 0;
                int grc = ok ? gr : 0;
                cp_async16(sbase + SA + r * 272 + c4 * 16, A16 + grc * 64 + c4 * 4, ok);
            }
        }
        CP_COMMIT();
    }

    for (int idx = t; idx < 128 * 128; idx += 256) {
        int k = idx >> 7, n = idx & 127;
        *(unsigned short*)(smem + SWA + (k * 136 + n) * 2) =
            __half_as_ushort(__float2half_rn(W1a[idx]));
        *(unsigned short*)(smem + SWB + (k * 136 + n) * 2) =
            __half_as_ushort(__float2half_rn(W1b[idx]));
    }
    if (t < 128) { sBias1[t] = b1a[t]; sBias2[t] = b1b[t]; }

    int lrow = (lane & 7) + ((lane >> 3) & 1) * 8;
    int lcol = (lane >> 4) * 8;
    uint32_t lOff = (uint32_t)(lrow * 136 + lcol) * 2;
    int er = lane >> 2;
    int ec = 2 * (lane & 3);

    for (int tile = blockIdx.x; tile < NTILES; tile += gridDim.x) {
        int row0 = tile << 7;
        CP_WAIT0();
        __syncthreads();

        float c[2][8][4];
        mainloop_f16(sbase, SWA, lOff, m0, n0, c);
        __syncthreads();

#pragma unroll
        for (int mh = 0; mh < 2; mh++)
#pragma unroll
            for (int j = 0; j < 8; j++) {
                int n = n0 + j * 8 + ec;
                float b0 = sBias1[n], b1 = sBias1[n + 1];
                float* cc = c[mh][j];
                int r0 = m0 + mh * 16 + er;
                *(unsigned*)(smem + SA + r0 * 272 + n * 2) =
                    pack_h2(fmaxf(cc[0] + b0, 0.f), fmaxf(cc[1] + b1, 0.f));
                *(unsigned*)(smem + SA + (r0 + 8) * 272 + n * 2) =
                    pack_h2(fmaxf(cc[2] + b0, 0.f), fmaxf(cc[3] + b1, 0.f));
            }
        __syncthreads();

        mainloop_f16(sbase, SWB, lOff, m0, n0, c);
        __syncthreads();

#pragma unroll
        for (int mh = 0; mh < 2; mh++)
#pragma unroll
            for (int j = 0; j < 8; j++) {
                int n = n0 + j * 8 + ec;
                float b0 = sBias2[n], b1 = sBias2[n + 1];
                float* cc = c[mh][j];
                int r0 = m0 + mh * 16 + er;
                *(unsigned*)(smem + SA + r0 * 272 + n * 2) =
                    pack_h2(fmaxf(cc[0] + b0, 0.f), fmaxf(cc[1] + b1, 0.f));
                *(unsigned*)(smem + SA + (r0 + 8) * 272 + n * 2) =
                    pack_h2(fmaxf(cc[2] + b0, 0.f), fmaxf(cc[3] + b1, 0.f));
            }
        if (t < 128) {
            int gr = row0 + t;
            sB[t] = (gr < M) ? load_index(batch, gr, is64) : -1;
        }
        __syncthreads();

        if (t < 128) {
            float s = 0.f, q = 0.f, run = 0.f;
            int cur = sB[0];
            for (int r = 0; r < 128; r++) {
                int b = sB[r];
                if (b != cur) {
                    if (cur >= 0) atomicAdd(&g_gsum[cur * NF + t], run);
                    run = 0.f;
                    cur = b;
                }
                if (b >= 0) {
                    float v = __half2float(
                        *(const __half*)(smem + SA + r * 272 + t * 2));
                    run += v;
                    s += v;
                    q += v * v;
                }
            }
            if (cur >= 0) atomicAdd(&g_gsum[cur * NF + t], run);
            atomicAdd(&g_stats[t], s);
            atomicAdd(&g_stats[128 + t], q);
        }
        __syncthreads();

        {
            int nt = tile + gridDim.x;
            if (nt < NTILES) {
                int row0n = nt << 7;
                for (int idx = t; idx < 2048; idx += 256) {
                    int r = idx >> 4, c4 = idx & 15;
                    int gr = row0n + r;
                    int ok = (gr < M) ? 16 : 0;
                    int grc = ok ? gr : 0;
                    cp_async16(sbase + SA + r * 272 + c4 * 16,
                               A16 + grc * 64 + c4 * 4, ok);
                }
            }
            CP_COMMIT();
        }
    }
}

// ---------------- fused: BN-affine pool + recurrence + output MLP ----------
__global__ __launch_bounds__(512, 1) void recur_mlp_kernel(
        const void* __restrict__ batch,
        const float* __restrict__ gamma, const float* __restrict__ beta,
        const float* __restrict__ Wl1, const float* __restrict__ bl1,
        const float* __restrict__ Wl2, const float* __restrict__ bl2,
        const float* __restrict__ Wm1, const float* __restrict__ bm1,
        const float* __restrict__ Wm2, const float* __restrict__ bm2,
        float* __restrict__ out) {
    __shared__ float cat[256];
    __shared__ float part[512];
    __shared__ float hid[DIM];
    __shared__ int se[3];
    int t = threadIdx.x;
    int g = blockIdx.x;
    int c = t & 127;
    int q = t >> 7;
    int is64 = probe_is64(batch);

    if (t < 2) {
        int target = g + t;
        int lo = 0, hi = N_NODES;
        while (lo < hi) {
            int mid = (lo + hi) >> 1;
            int b = load_index(batch, mid, is64);
            if (b < target) lo = mid + 1; else hi = mid;
        }
        se[t] = lo;
    }

    unsigned long long wp[32];
    {
        const float* Wsrc = (c < 64) ? (Wl2 + c) : (Wl1 + (c - 64));
        int kbase = q * 64;
#pragma unroll
        for (int i = 0; i < 32; i++) {
            float w0 = Wsrc[(kbase + 2 * i) * 64];
            float w1 = Wsrc[(kbase + 2 * i + 1) * 64];
            wp[i] = pack_f32x2(w0, w1);
        }
    }
    float bias = 0.f;
    if (t < 128) bias = (t < 64) ? bl2[t] : bl1[t - 64];

    float ss = 0.f, sq = 0.f, gsv = 0.f;
    if (t < 128) {
        ss = g_stats[t];
        sq = g_stats[128 + t];
        gsv = g_gsum[g * NF + t];
        g_gsum[g * NF + t] = 0.f;
    }
    __syncthreads();
    if (t == 0) {
        __threadfence();
        int k = atomicAdd(&g_tickR, 1);
        se[2] = (k == N_GRAPHS - 1);
    }
    __syncthreads();
    if (se[2]) {
        if (t < 256) g_stats[t] = 0.f;
        if (t == 0) g_tickR = 0;
    }

    if (t < 128) {
        int cnt = se[1] - se[0];
        float mu = ss / (float)N_NODES;
        float var = sq / (float)N_NODES - mu * mu;
        float val = 0.f;
        if (cnt > 0) {
            float m = gsv / (float)cnt;
            val = gamma[t] * (m - mu) * rsqrtf(var + BN_EPS) + beta[t];
        }
        cat[t] = val;
        cat[128 + t] = val;
    }
    __syncthreads();

    for (int it = 0; it < N_ITERS; it++) {
        const float* ck = &cat[q * 64];
        unsigned long long acc0 = pack_f32x2(0.f, 0.f);
        unsigned long long acc1 = pack_f32x2(0.f, 0.f);
#pragma unroll
        for (int i = 0; i < 32; i += 2) {
            unsigned long long c0 = *(const unsigned long long*)&ck[2 * i];
            unsigned long long c1 = *(const unsigned long long*)&ck[2 * i + 2];
            asm("fma.rn.f32x2 %0, %1, %2, %0;" : "+l"(acc0) : "l"(wp[i]), "l"(c0));
            asm("fma.rn.f32x2 %0, %1, %2, %0;" : "+l"(acc1) : "l"(wp[i + 1]), "l"(c1));
        }
        float l0, h0, l1, h1;
        unpack_f32x2(acc0, l0, h0);
        unpack_f32x2(acc1, l1, h1);
        part[t] = (l0 + h0) + (l1 + h1);
        __syncthreads();
        if (t < 128) {
            float o = part[t] + part[t + 128] + part[t + 256] + part[t + 384] + bias;
            float v = (t < 64) ? tanhf(o) : (1.0f / (1.0f + expf(-o)));
            cat[128 + t] = v;
        }
        __syncthreads();
    }

    if (t < DIM) {
        float a = bm1[t];
        const float* h = &cat[128];
#pragma unroll 8
        for (int k = 0; k < NF; k++) a += h[k] * Wm1[k * DIM + t];
        hid[t] = fmaxf(a, 0.f);
    }
    __syncthreads();
    if (t < N_OUT) {
        float a = bm2[t];
        for (int k = 0; k < DIM; k++) a += hid[k] * Wm2[k * N_OUT + t];
        out[g * N_OUT + t] = a;
    }
}

// ---------------- host ----------------
extern "C" void kernel_launch(void* const* d_in, const int* in_sizes, int n_in,
                              void* d_out, int out_size) {
    const float* x     = (const float*)d_in[0];
    const void*  ei    = d_in[1];
    const void*  batch = d_in[2];
    const float* W1a = (const float*)d_in[3];
    const float* b1a = (const float*)d_in[4];
    const float* W1b = (const float*)d_in[5];
    const float* b1b = (const float*)d_in[6];
    const float* gamma = (const float*)d_in[7];
    const float* beta  = (const float*)d_in[8];
    const float* Wl1 = (const float*)d_in[9];
    const float* bl1 = (const float*)d_in[10];
    const float* Wl2 = (const float*)d_in[11];
    const float* bl2 = (const float*)d_in[12];
    const float* Wm1 = (const float*)d_in[13];
    const float* bm1 = (const float*)d_in[14];
    const float* Wm2 = (const float*)d_in[15];
    const float* bm2 = (const float*)d_in[16];
    float* out = (float*)d_out;

    void* p_a16;
    cudaGetSymbolAddress(&p_a16, g_a16);

    cudaFuncSetAttribute(gemm_fused_kernel,
                         cudaFuncAttributeMaxDynamicSharedMemorySize, GEMM_SMEM);

    count_kernel<<<CNT_BLK + CVT_BLK, 256>>>(ei, (const float4*)x);
    scanAB_kernel<<<SCAN_NBLK, 256>>>();
    scatter_kernel<<<512, 256>>>(ei);
    agg_kernel<<<(N_NODES + 7) / 8, 256>>>();
    gemm_fused_kernel<<<296, 256, GEMM_SMEM>>>(
        (const unsigned*)p_a16, W1a, b1a, W1b, b1b, batch, N_NODES);
    recur_mlp_kernel<<<N_GRAPHS, 512>>>(
        batch, gamma, beta, Wl1, bl1, Wl2, bl2, Wm1, bm1, Wm2, bm2, out);
}